// round 14
// baseline (speedup 1.0000x reference)
#include <cuda_runtime.h>
#include <math.h>

#define D        128
#define K_NEG    4
#define T        8            // same-relation triples per score block
#define NVEC     (5 * T)      // 40 u-vectors per block
#define THREADS  256          // 8 warps = 8 vec-groups of 5 vectors
#define MAX_M    16384
#define MAX_REL  256
#define NPAD_MAX (MAX_M + MAX_REL * T)

// packed f32x2 FMA and unpack
#define FMA_F32X2(d, a, b, c) \
    asm("fma.rn.f32x2 %0, %1, %2, %3;" : "=l"(d) : "l"(a), "l"(b), "l"(c))
#define UNPACK_F32X2(lo, hi, in) \
    asm("mov.b64 {%0, %1}, %2;" : "=f"(lo), "=f"(hi) : "l"(in))

// dynamic smem layout (bytes)
#define SMEM_R   0                         // Rs: 32 c4-blocks x 128 rows x float4 = 64 KB
#define SMEM_U   (SMEM_R + D * D * 4)      // u: 40 x 128 f32 = 20 KB
#define SMEM_E   (SMEM_U + NVEC * D * 4)   // evec: 128 f32
#define SMEM_SC  (SMEM_E + D * 4)          // per-vec scores: 40 f32
#define SMEM_SZ  (SMEM_SC + NVEC * 4)      // = 86,848 B

// ---- allocation-free scratch ----
__device__ int g_order[NPAD_MAX];

// K0: fused prologue, ONE block: zero out[0], smem histogram, warp-parallel
// padded exclusive scan, scatter + pad-fill + tail poison.
__global__ void __launch_bounds__(1024) kg_prologue_kernel(
    const int* __restrict__ rel_ids, float* __restrict__ out,
    int M, int n_rel, int npad)
{
    __shared__ int scnt[MAX_REL];
    __shared__ int soff[MAX_REL];
    __shared__ int spos[MAX_REL];
    __shared__ int stotal;
    const int tid = threadIdx.x;

    if (tid == 0) out[0] = 0.0f;
    for (int i = tid; i < n_rel; i += 1024) { scnt[i] = 0; spos[i] = 0; }
    __syncthreads();

    for (int m = tid; m < M; m += 1024) atomicAdd(&scnt[rel_ids[m]], 1);
    __syncthreads();

    if (n_rel <= 64) {
        if (tid < 32) {
            const int lane = tid;
            const int p0 = (lane < n_rel)
                ? ((scnt[lane] + T - 1) / T) * T : 0;
            const int p1 = (lane + 32 < n_rel)
                ? ((scnt[lane + 32] + T - 1) / T) * T : 0;
            int c0 = p0, c1 = p1;
            #pragma unroll
            for (int off = 1; off < 32; off <<= 1) {
                int n0 = __shfl_up_sync(0xFFFFFFFFu, c0, off);
                int n1 = __shfl_up_sync(0xFFFFFFFFu, c1, off);
                if (lane >= off) { c0 += n0; c1 += n1; }
            }
            const int tot0 = __shfl_sync(0xFFFFFFFFu, c0, 31);
            const int tot1 = __shfl_sync(0xFFFFFFFFu, c1, 31);
            if (lane < n_rel) soff[lane] = c0 - p0;
            if (lane + 32 < n_rel) soff[lane + 32] = tot0 + c1 - p1;
            if (lane == 31) stotal = tot0 + tot1;
        }
    } else if (tid == 0) {
        int acc = 0;
        for (int r = 0; r < n_rel; r++) {
            soff[r] = acc;
            acc += ((scnt[r] + T - 1) / T) * T;
        }
        stotal = acc;
    }
    __syncthreads();

    for (int m = tid; m < M; m += 1024) {
        const int r = rel_ids[m];
        const int p = atomicAdd(&spos[r], 1);
        g_order[soff[r] + p] = m;
    }
    {
        const int r = tid / T, s = tid % T;
        for (int rr = r; rr < n_rel; rr += 1024 / T) {
            const int cnt = scnt[rr];
            const int pad = ((cnt + T - 1) / T) * T;
            const int slot = cnt + s;
            if (slot < pad) g_order[soff[rr] + slot] = -1;
        }
    }
    for (int i = stotal + tid; i < npad; i += 1024) g_order[i] = -1;
}

// K1: score, 2-D register tiling + software-pipelined mainloop.
// Block = one T-slot same-relation tile, 256 threads.
// warp = vec-group (5 vectors); lane l owns rows {l, 32+l, 64+l, 96+l}.
// Iteration c4 computes with registers prefetched at c4-1, while issuing
// the LDS for c4+1 -> 29-cyc LDS latency hidden behind 40 FFMA2 issues.
__global__ void __launch_bounds__(THREADS, 2) kg_score_kernel(
    const float* __restrict__ mol_emb,        // [B, D]
    const float* __restrict__ entity_emb,     // [N_ENT, D]
    const float* __restrict__ relation_emb,   // [N_REL, D]
    const float* __restrict__ relation_matrix,// [N_REL, D, D]
    const int*   __restrict__ tail_ids,       // [M]
    const int*   __restrict__ rel_ids,        // [M]
    const int*   __restrict__ neg_indices,    // [M, K]
    float* __restrict__ out,
    int n_per_b, float invB)
{
    extern __shared__ __align__(16) char smem[];
    float4* Rs = reinterpret_cast<float4*>(smem + SMEM_R);
    float*  uv = reinterpret_cast<float*>(smem + SMEM_U);
    float*  ev = reinterpret_cast<float*>(smem + SMEM_E);
    float*  sc = reinterpret_cast<float*>(smem + SMEM_SC);

    __shared__ int   sm_m[T];
    __shared__ int   sm_b[T];
    __shared__ int   sm_row[NVEC];
    __shared__ int   sm_rel;
    __shared__ float lsum[T];

    const int tid = threadIdx.x;

    if (tid < T) {
        const int m = g_order[blockIdx.x * T + tid];
        sm_m[tid] = m;
        sm_b[tid] = (m >= 0) ? (m / n_per_b) : -1;
    }
    __syncthreads();

    if (tid < NVEC) {
        const int i = tid / 5, q = tid - i * 5;
        const int m = sm_m[i];
        int row = -1;
        if (m >= 0)
            row = (q == 0) ? tail_ids[m]
                           : tail_ids[neg_indices[m * K_NEG + (q - 1)]];
        sm_row[tid] = row;
        if (tid == 0) {
            int r = -1;
            #pragma unroll
            for (int j = 0; j < T; j++)
                if (r < 0 && sm_m[j] >= 0) r = rel_ids[sm_m[j]];
            sm_rel = r;
        }
    }
    __syncthreads();

    const int r_id = sm_rel;
    if (r_id < 0) return;            // dead padding block (uniform exit)

    // ---- stage R (64 KB) transposed at float4 granularity: Rs[c4*D+row] ----
    {
        const float4* Rg = reinterpret_cast<const float4*>(
            relation_matrix + (size_t)r_id * D * D);
        #pragma unroll 4
        for (int idx = tid; idx < D * (D / 4); idx += THREADS) {
            const int c4 = idx >> 7;          // 0..31
            const int row = idx & 127;
            Rs[c4 * D + row] = Rg[row * (D / 4) + c4];
        }
    }
    if (tid < D) ev[tid] = relation_emb[(size_t)r_id * D + tid];
    // ---- stage u vectors: 2 vectors at a time across 256 threads ----
    {
        const int c = tid & 127;
        const int jo = tid >> 7;              // 0 or 1
        for (int j = jo; j < NVEC; j += 2) {
            const int i = j / 5;
            const int b = sm_b[i];
            const float h = (b >= 0) ? mol_emb[(size_t)b * D + c] : 0.f;
            const int row = sm_row[j];
            uv[j * D + c] =
                (row >= 0) ? (h - entity_emb[(size_t)row * D + c]) : 0.f;
        }
    }
    __syncthreads();

    // ---- software-pipelined mainloop: 4 rows x 5 vecs, packed f32x2 ----
    const int l  = tid & 31;
    const int vg = tid >> 5;                  // 0..7
    const ulonglong2* Rs2 = reinterpret_cast<const ulonglong2*>(smem + SMEM_R);
    const ulonglong2* u2  = reinterpret_cast<const ulonglong2*>(smem + SMEM_U);

    unsigned long long acc[4][5];
    #pragma unroll
    for (int i = 0; i < 4; i++)
        #pragma unroll
        for (int q = 0; q < 5; q++) acc[i][q] = 0ull;

    ulonglong2 rc[4], vc[5];                  // current operands
    // preload c4 = 0
    #pragma unroll
    for (int i = 0; i < 4; i++) rc[i] = Rs2[32 * i + l];
    #pragma unroll
    for (int q = 0; q < 5; q++) vc[q] = u2[(5 * vg + q) * (D / 4)];

    #pragma unroll 2
    for (int c4 = 0; c4 < D / 4; c4++) {
        // prefetch next iteration (wraps harmlessly on last)
        const int n4 = (c4 + 1) & 31;
        ulonglong2 rn[4], vn[5];
        #pragma unroll
        for (int i = 0; i < 4; i++) rn[i] = Rs2[n4 * D + 32 * i + l];
        #pragma unroll
        for (int q = 0; q < 5; q++) vn[q] = u2[(5 * vg + q) * (D / 4) + n4];

        // x-phase: 20 independent FFMA2
        #pragma unroll
        for (int q = 0; q < 5; q++) {
            FMA_F32X2(acc[0][q], rc[0].x, vc[q].x, acc[0][q]);
            FMA_F32X2(acc[1][q], rc[1].x, vc[q].x, acc[1][q]);
            FMA_F32X2(acc[2][q], rc[2].x, vc[q].x, acc[2][q]);
            FMA_F32X2(acc[3][q], rc[3].x, vc[q].x, acc[3][q]);
        }
        // y-phase: 20 independent FFMA2
        #pragma unroll
        for (int q = 0; q < 5; q++) {
            FMA_F32X2(acc[0][q], rc[0].y, vc[q].y, acc[0][q]);
            FMA_F32X2(acc[1][q], rc[1].y, vc[q].y, acc[1][q]);
            FMA_F32X2(acc[2][q], rc[2].y, vc[q].y, acc[2][q]);
            FMA_F32X2(acc[3][q], rc[3].y, vc[q].y, acc[3][q]);
        }

        #pragma unroll
        for (int i = 0; i < 4; i++) rc[i] = rn[i];
        #pragma unroll
        for (int q = 0; q < 5; q++) vc[q] = vn[q];
    }

    // ---- epilogue: complete dots in-register; shuffle-reduce per vec ----
    const float e0 = ev[l];
    const float e1 = ev[32 + l];
    const float e2 = ev[64 + l];
    const float e3 = ev[96 + l];
    #pragma unroll
    for (int q = 0; q < 5; q++) {
        float lo, hi, d, s = 0.f;
        UNPACK_F32X2(lo, hi, acc[0][q]); d = (lo + hi) + e0; s = fmaf(d, d, s);
        UNPACK_F32X2(lo, hi, acc[1][q]); d = (lo + hi) + e1; s = fmaf(d, d, s);
        UNPACK_F32X2(lo, hi, acc[2][q]); d = (lo + hi) + e2; s = fmaf(d, d, s);
        UNPACK_F32X2(lo, hi, acc[3][q]); d = (lo + hi) + e3; s = fmaf(d, d, s);
        #pragma unroll
        for (int off = 16; off > 0; off >>= 1)
            s += __shfl_down_sync(0xFFFFFFFFu, s, off);
        if (l == 0) sc[5 * vg + q] = s;      // vec (5*vg+q) owned by warp vg
    }
    __syncthreads();

    if (tid < T) {
        const int m = sm_m[tid];
        float loss = 0.f;
        if (m >= 0) {
            const float pos = sc[5 * tid];
            const float neg_mean = (sc[5 * tid + 1] + sc[5 * tid + 2] +
                                    sc[5 * tid + 3] + sc[5 * tid + 4]) * 0.25f;
            const float x = neg_mean - pos;
            const float sig = 1.0f / (1.0f + expf(-x)); // -inf -> 0, ref-compatible
            loss = -logf(sig + 1e-12f);
        }
        lsum[tid] = loss;
    }
    __syncthreads();
    if (tid == 0) {
        float blk = 0.f;
        #pragma unroll
        for (int i = 0; i < T; i++) blk += lsum[i];
        atomicAdd(out, blk * invB);
    }
}

extern "C" void kernel_launch(void* const* d_in, const int* in_sizes, int n_in,
                              void* d_out, int out_size)
{
    const float* mol_emb         = (const float*)d_in[0];
    const float* entity_emb      = (const float*)d_in[1];
    const float* relation_emb    = (const float*)d_in[2];
    const float* relation_matrix = (const float*)d_in[3];
    const int*   tail_ids        = (const int*)d_in[4];
    const int*   rel_ids         = (const int*)d_in[5];
    const int*   neg_indices     = (const int*)d_in[6];
    float* out = (float*)d_out;

    const int B = in_sizes[0] / D;                 // 512
    int n_rel = in_sizes[2] / D;                   // 64
    if (n_rel > MAX_REL) n_rel = MAX_REL;
    int M = in_sizes[5];                           // 8192
    if (M > MAX_M) M = MAX_M;
    const int n_per_b = M / B;                     // 16

    const int NB   = M / T + n_rel;                // 1088 padded tiles
    const int npad = NB * T;

    // opt-in to >48KB dynamic smem (idempotent; immediate, not captured)
    cudaFuncSetAttribute(kg_score_kernel,
                         cudaFuncAttributeMaxDynamicSharedMemorySize, SMEM_SZ);

    kg_prologue_kernel<<<1, 1024>>>(rel_ids, out, M, n_rel, npad);
    kg_score_kernel<<<NB, THREADS, SMEM_SZ>>>(
        mol_emb, entity_emb, relation_emb, relation_matrix,
        tail_ids, rel_ids, neg_indices, out, n_per_b, 1.0f / (float)B);
}

// round 16
// speedup vs baseline: 1.1340x; 1.1340x over previous
#include <cuda_runtime.h>
#include <math.h>

#define D        128
#define K_NEG    4
#define T        8            // same-relation triples per score tile
#define NVEC     (5 * T)      // 40 u-vectors per tile
#define THREADS  256          // 8 warps = 8 vec-groups of 5 vectors
#define NBLOCKS  296          // persistent: 2 per SM, one wave
#define MAX_M    16384
#define MAX_REL  256
#define NPAD_MAX (MAX_M + MAX_REL * T)

// packed f32x2 FMA and unpack
#define FMA_F32X2(d, a, b, c) \
    asm("fma.rn.f32x2 %0, %1, %2, %3;" : "=l"(d) : "l"(a), "l"(b), "l"(c))
#define UNPACK_F32X2(lo, hi, in) \
    asm("mov.b64 {%0, %1}, %2;" : "=f"(lo), "=f"(hi) : "l"(in))

// dynamic smem layout (bytes)
#define SMEM_R   0                         // Rs: 32 c4-blocks x 128 rows x float4 = 64 KB
#define SMEM_U   (SMEM_R + D * D * 4)      // u: 40 x 128 f32 = 20 KB
#define SMEM_E   (SMEM_U + NVEC * D * 4)   // evec: 128 f32
#define SMEM_SC  (SMEM_E + D * 4)          // per-vec scores: 40 f32
#define SMEM_SZ  (SMEM_SC + NVEC * 4)      // = 86,848 B

// ---- allocation-free scratch ----
__device__ int g_order[NPAD_MAX];

// K0: fused prologue, ONE block: zero out[0], smem histogram, warp-parallel
// padded exclusive scan, scatter + pad-fill + tail poison.
__global__ void __launch_bounds__(1024) kg_prologue_kernel(
    const int* __restrict__ rel_ids, float* __restrict__ out,
    int M, int n_rel, int npad)
{
    __shared__ int scnt[MAX_REL];
    __shared__ int soff[MAX_REL];
    __shared__ int spos[MAX_REL];
    __shared__ int stotal;
    const int tid = threadIdx.x;

    if (tid == 0) out[0] = 0.0f;
    for (int i = tid; i < n_rel; i += 1024) { scnt[i] = 0; spos[i] = 0; }
    __syncthreads();

    for (int m = tid; m < M; m += 1024) atomicAdd(&scnt[rel_ids[m]], 1);
    __syncthreads();

    if (n_rel <= 64) {
        if (tid < 32) {
            const int lane = tid;
            const int p0 = (lane < n_rel)
                ? ((scnt[lane] + T - 1) / T) * T : 0;
            const int p1 = (lane + 32 < n_rel)
                ? ((scnt[lane + 32] + T - 1) / T) * T : 0;
            int c0 = p0, c1 = p1;
            #pragma unroll
            for (int off = 1; off < 32; off <<= 1) {
                int n0 = __shfl_up_sync(0xFFFFFFFFu, c0, off);
                int n1 = __shfl_up_sync(0xFFFFFFFFu, c1, off);
                if (lane >= off) { c0 += n0; c1 += n1; }
            }
            const int tot0 = __shfl_sync(0xFFFFFFFFu, c0, 31);
            const int tot1 = __shfl_sync(0xFFFFFFFFu, c1, 31);
            if (lane < n_rel) soff[lane] = c0 - p0;
            if (lane + 32 < n_rel) soff[lane + 32] = tot0 + c1 - p1;
            if (lane == 31) stotal = tot0 + tot1;
        }
    } else if (tid == 0) {
        int acc = 0;
        for (int r = 0; r < n_rel; r++) {
            soff[r] = acc;
            acc += ((scnt[r] + T - 1) / T) * T;
        }
        stotal = acc;
    }
    __syncthreads();

    for (int m = tid; m < M; m += 1024) {
        const int r = rel_ids[m];
        const int p = atomicAdd(&spos[r], 1);
        g_order[soff[r] + p] = m;
    }
    {
        const int r = tid / T, s = tid % T;
        for (int rr = r; rr < n_rel; rr += 1024 / T) {
            const int cnt = scnt[rr];
            const int pad = ((cnt + T - 1) / T) * T;
            const int slot = cnt + s;
            if (slot < pad) g_order[soff[rr] + slot] = -1;
        }
    }
    for (int i = stotal + tid; i < npad; i += 1024) g_order[i] = -1;
}

// K1: persistent score kernel. Each block processes a CONTIGUOUS chunk of
// T-slot tiles; tiles are relation-major, so consecutive tiles usually share
// a relation and the 64 KB R staging is skipped (cur_rel tracking).
// Per tile: 4 rows x 5 vecs per thread, packed fma.rn.f32x2 (R13 mainloop).
__global__ void __launch_bounds__(THREADS, 2) kg_score_kernel(
    const float* __restrict__ mol_emb,        // [B, D]
    const float* __restrict__ entity_emb,     // [N_ENT, D]
    const float* __restrict__ relation_emb,   // [N_REL, D]
    const float* __restrict__ relation_matrix,// [N_REL, D, D]
    const int*   __restrict__ tail_ids,       // [M]
    const int*   __restrict__ rel_ids,        // [M]
    const int*   __restrict__ neg_indices,    // [M, K]
    float* __restrict__ out,
    int n_per_b, float invB, int nb_tiles, int chunk)
{
    extern __shared__ __align__(16) char smem[];
    float4* Rs = reinterpret_cast<float4*>(smem + SMEM_R);
    float*  uv = reinterpret_cast<float*>(smem + SMEM_U);
    float*  ev = reinterpret_cast<float*>(smem + SMEM_E);
    float*  sc = reinterpret_cast<float*>(smem + SMEM_SC);

    __shared__ int   sm_m[T];
    __shared__ int   sm_b[T];
    __shared__ int   sm_row[NVEC];
    __shared__ int   sm_rel;
    __shared__ float lsum[T];

    const int tid = threadIdx.x;
    const int l   = tid & 31;
    const int vg  = tid >> 5;                 // 0..7
    const ulonglong2* Rs2 = reinterpret_cast<const ulonglong2*>(smem + SMEM_R);
    const ulonglong2* u2  = reinterpret_cast<const ulonglong2*>(smem + SMEM_U);

    int cur_rel = -1;
    const int t0 = blockIdx.x * chunk;
    int t1 = t0 + chunk;
    if (t1 > nb_tiles) t1 = nb_tiles;

    for (int tile = t0; tile < t1; tile++) {
        __syncthreads();                      // previous tile fully consumed

        if (tid < T) {
            const int m = g_order[tile * T + tid];
            sm_m[tid] = m;
            sm_b[tid] = (m >= 0) ? (m / n_per_b) : -1;
        }
        __syncthreads();

        if (tid < NVEC) {
            const int i = tid / 5, q = tid - i * 5;
            const int m = sm_m[i];
            int row = -1;
            if (m >= 0)
                row = (q == 0) ? tail_ids[m]
                               : tail_ids[neg_indices[m * K_NEG + (q - 1)]];
            sm_row[tid] = row;
            if (tid == 0) {
                int r = -1;
                #pragma unroll
                for (int j = 0; j < T; j++)
                    if (r < 0 && sm_m[j] >= 0) r = rel_ids[sm_m[j]];
                sm_rel = r;
            }
        }
        __syncthreads();

        const int r_id = sm_rel;
        if (r_id < 0) continue;               // dead padding tile (uniform)

        // ---- stage R only when the relation changes ----
        if (r_id != cur_rel) {
            const float4* Rg = reinterpret_cast<const float4*>(
                relation_matrix + (size_t)r_id * D * D);
            #pragma unroll 4
            for (int idx = tid; idx < D * (D / 4); idx += THREADS) {
                const int c4 = idx >> 7;      // 0..31
                const int row = idx & 127;
                Rs[c4 * D + row] = Rg[row * (D / 4) + c4];
            }
            if (tid < D) ev[tid] = relation_emb[(size_t)r_id * D + tid];
            cur_rel = r_id;
        }
        // ---- stage u vectors: 2 vectors at a time across 256 threads ----
        {
            const int c = tid & 127;
            const int jo = tid >> 7;          // 0 or 1
            for (int j = jo; j < NVEC; j += 2) {
                const int i = j / 5;
                const int b = sm_b[i];
                const float h = (b >= 0) ? mol_emb[(size_t)b * D + c] : 0.f;
                const int row = sm_row[j];
                uv[j * D + c] =
                    (row >= 0) ? (h - entity_emb[(size_t)row * D + c]) : 0.f;
            }
        }
        __syncthreads();

        // ---- mainloop: 4 rows x 5 vecs per thread, packed f32x2 ----
        unsigned long long acc[4][5];
        #pragma unroll
        for (int i = 0; i < 4; i++)
            #pragma unroll
            for (int q = 0; q < 5; q++) acc[i][q] = 0ull;

        #pragma unroll 2
        for (int c4 = 0; c4 < D / 4; c4++) {
            const ulonglong2 r0 = Rs2[c4 * D + l];
            const ulonglong2 r1 = Rs2[c4 * D + 32 + l];
            const ulonglong2 r2 = Rs2[c4 * D + 64 + l];
            const ulonglong2 r3 = Rs2[c4 * D + 96 + l];
            #pragma unroll
            for (int q = 0; q < 5; q++) {
                const ulonglong2 v = u2[(5 * vg + q) * (D / 4) + c4];
                FMA_F32X2(acc[0][q], r0.x, v.x, acc[0][q]);
                FMA_F32X2(acc[0][q], r0.y, v.y, acc[0][q]);
                FMA_F32X2(acc[1][q], r1.x, v.x, acc[1][q]);
                FMA_F32X2(acc[1][q], r1.y, v.y, acc[1][q]);
                FMA_F32X2(acc[2][q], r2.x, v.x, acc[2][q]);
                FMA_F32X2(acc[2][q], r2.y, v.y, acc[2][q]);
                FMA_F32X2(acc[3][q], r3.x, v.x, acc[3][q]);
                FMA_F32X2(acc[3][q], r3.y, v.y, acc[3][q]);
            }
        }

        // ---- epilogue: complete dots in-register; shuffle-reduce per vec ----
        const float e0 = ev[l];
        const float e1 = ev[32 + l];
        const float e2 = ev[64 + l];
        const float e3 = ev[96 + l];
        #pragma unroll
        for (int q = 0; q < 5; q++) {
            float lo, hi, d, s = 0.f;
            UNPACK_F32X2(lo, hi, acc[0][q]); d = (lo + hi) + e0; s = fmaf(d, d, s);
            UNPACK_F32X2(lo, hi, acc[1][q]); d = (lo + hi) + e1; s = fmaf(d, d, s);
            UNPACK_F32X2(lo, hi, acc[2][q]); d = (lo + hi) + e2; s = fmaf(d, d, s);
            UNPACK_F32X2(lo, hi, acc[3][q]); d = (lo + hi) + e3; s = fmaf(d, d, s);
            #pragma unroll
            for (int off = 16; off > 0; off >>= 1)
                s += __shfl_down_sync(0xFFFFFFFFu, s, off);
            if (l == 0) sc[5 * vg + q] = s;
        }
        __syncthreads();

        if (tid < T) {
            const int m = sm_m[tid];
            float loss = 0.f;
            if (m >= 0) {
                const float pos = sc[5 * tid];
                const float neg_mean = (sc[5 * tid + 1] + sc[5 * tid + 2] +
                                        sc[5 * tid + 3] + sc[5 * tid + 4]) * 0.25f;
                const float x = neg_mean - pos;
                const float sig = 1.0f / (1.0f + expf(-x)); // -inf -> 0
                loss = -logf(sig + 1e-12f);
            }
            lsum[tid] = loss;
        }
        __syncthreads();
        if (tid == 0) {
            float blk = 0.f;
            #pragma unroll
            for (int i = 0; i < T; i++) blk += lsum[i];
            atomicAdd(out, blk * invB);
        }
    }
}

extern "C" void kernel_launch(void* const* d_in, const int* in_sizes, int n_in,
                              void* d_out, int out_size)
{
    const float* mol_emb         = (const float*)d_in[0];
    const float* entity_emb      = (const float*)d_in[1];
    const float* relation_emb    = (const float*)d_in[2];
    const float* relation_matrix = (const float*)d_in[3];
    const int*   tail_ids        = (const int*)d_in[4];
    const int*   rel_ids         = (const int*)d_in[5];
    const int*   neg_indices     = (const int*)d_in[6];
    float* out = (float*)d_out;

    const int B = in_sizes[0] / D;                 // 512
    int n_rel = in_sizes[2] / D;                   // 64
    if (n_rel > MAX_REL) n_rel = MAX_REL;
    int M = in_sizes[5];                           // 8192
    if (M > MAX_M) M = MAX_M;
    const int n_per_b = M / B;                     // 16

    const int NB    = M / T + n_rel;               // 1088 padded tiles
    const int npad  = NB * T;
    const int chunk = (NB + NBLOCKS - 1) / NBLOCKS; // contiguous tiles/block

    // opt-in to >48KB dynamic smem (idempotent; immediate, not captured)
    cudaFuncSetAttribute(kg_score_kernel,
                         cudaFuncAttributeMaxDynamicSharedMemorySize, SMEM_SZ);

    kg_prologue_kernel<<<1, 1024>>>(rel_ids, out, M, n_rel, npad);
    kg_score_kernel<<<NBLOCKS, THREADS, SMEM_SZ>>>(
        mol_emb, entity_emb, relation_emb, relation_matrix,
        tail_ids, rel_ids, neg_indices, out, n_per_b, 1.0f / (float)B,
        NB, chunk);
}